// round 3
// baseline (speedup 1.0000x reference)
#include <cuda_runtime.h>
#include <math.h>

// ---------------------------------------------------------------------------
// MoE sparse pipeline:
//   router -> scan -> scatter -> grouped GEMM1 (gelu) -> grouped GEMM2 -> combine
// fp32 throughout for rel_err safety this round.
// ---------------------------------------------------------------------------

#define DD    1024              // in_features
#define HH    4096              // hidden
#define EE    8                 // experts
#define NTOK  8192              // B*S
#define BMT   128               // GEMM row tile (expert padding granularity)
#define MAXROWS (NTOK*2 + EE*BMT)   // 17408

// -------- scratch (device globals: no allocation allowed) ------------------
__device__ int   g_counts[EE];
__device__ int   g_cursor[EE];
__device__ int   g_off[EE + 1];
__device__ int   g_total;
__device__ int   g_tok[MAXROWS];         // slot -> token id (0 for padding)
__device__ int   g_idx[NTOK * 2];        // (token,k) -> expert
__device__ int   g_slot[NTOK * 2];       // (token,k) -> slot
__device__ float g_p[NTOK * 2];          // (token,k) -> gate prob
__device__ float g_h[(size_t)MAXROWS * HH];   // hidden activations (~285MB)
__device__ float g_o[(size_t)MAXROWS * DD];   // per-slot expert outputs (~71MB)

// ---------------------------------------------------------------------------
__global__ void init_k() {
    int i = blockIdx.x * blockDim.x + threadIdx.x;
    if (i < EE) g_counts[i] = 0;
    if (i < MAXROWS) g_tok[i] = 0;   // grid sized to cover MAXROWS exactly
}

// one warp per token: logits = x@Wg + bg, softmax, top-2
__global__ void router_k(const float* __restrict__ x,
                         const float* __restrict__ Wg,
                         const float* __restrict__ bg) {
    int warp = (blockIdx.x * blockDim.x + threadIdx.x) >> 5;
    int lane = threadIdx.x & 31;
    if (warp >= NTOK) return;
    const float* xr = x + (size_t)warp * DD;

    float acc[EE];
#pragma unroll
    for (int e = 0; e < EE; e++) acc[e] = 0.f;
#pragma unroll
    for (int i = 0; i < DD / 32; i++) {
        float xv = xr[lane + 32 * i];
        const float* wr = Wg + (size_t)(lane + 32 * i) * EE;
#pragma unroll
        for (int e = 0; e < EE; e++) acc[e] += xv * wr[e];
    }
#pragma unroll
    for (int e = 0; e < EE; e++) {
#pragma unroll
        for (int o = 16; o > 0; o >>= 1)
            acc[e] += __shfl_xor_sync(0xffffffffu, acc[e], o);
    }
    if (lane == 0) {
        float l[EE];
        float m = -1e30f;
#pragma unroll
        for (int e = 0; e < EE; e++) { l[e] = acc[e] + bg[e]; m = fmaxf(m, l[e]); }
        float s = 0.f;
#pragma unroll
        for (int e = 0; e < EE; e++) s += expf(l[e] - m);
        // top-2 (first index wins ties, matching jax.lax.top_k)
        int i0 = 0;
#pragma unroll
        for (int e = 1; e < EE; e++) if (l[e] > l[i0]) i0 = e;
        int i1 = (i0 == 0) ? 1 : 0;
#pragma unroll
        for (int e = 0; e < EE; e++) if (e != i0 && l[e] > l[i1]) i1 = e;
        float p0 = expf(l[i0] - m) / s;
        float p1 = expf(l[i1] - m) / s;
        g_idx[warp * 2 + 0] = i0;  g_p[warp * 2 + 0] = p0;
        g_idx[warp * 2 + 1] = i1;  g_p[warp * 2 + 1] = p1;
        atomicAdd(&g_counts[i0], 1);
        atomicAdd(&g_counts[i1], 1);
    }
}

__global__ void scan_k() {
    if (threadIdx.x == 0) {
        int off = 0;
        for (int e = 0; e < EE; e++) {
            g_off[e] = off;
            g_cursor[e] = off;
            off += (g_counts[e] + BMT - 1) / BMT * BMT;   // pad to tile
        }
        g_off[EE] = off;
        g_total = off;
    }
}

__global__ void scatter_k() {
    int n = blockIdx.x * blockDim.x + threadIdx.x;
    if (n >= NTOK) return;
#pragma unroll
    for (int k = 0; k < 2; k++) {
        int e = g_idx[n * 2 + k];
        int pos = atomicAdd(&g_cursor[e], 1);
        g_tok[pos] = n;
        g_slot[n * 2 + k] = pos;
    }
}

// ---------------------------------------------------------------------------
// Grouped GEMM: C[rows x NDIM] = A[rows x KDIM] @ B_e[KDIM x NDIM] + bias_e
// MODE 1: A = gathered x rows, C = g_h, GELU epilogue
// MODE 2: A = g_h,             C = g_o, plain bias epilogue
// 128x128x8 tile, 256 threads, 8x8 microtile, smem double-buffered.
// ---------------------------------------------------------------------------
template <int KDIM, int NDIM, int MODE>
__global__ __launch_bounds__(256, 2)
void gemm_k(const float* __restrict__ Aarg,
            const float* __restrict__ Bw,
            const float* __restrict__ bias) {
    const int row0 = blockIdx.y * BMT;
    if (row0 >= g_total) return;
    int e = 0;
    while (row0 >= g_off[e + 1]) ++e;

    __shared__ float As[2][8][BMT];
    __shared__ float Bs[2][8][128];
    __shared__ int   ts[BMT];

    const int tid = threadIdx.x;
    const float* A = (MODE == 1) ? Aarg : g_h;
    float* Cout    = (MODE == 1) ? g_h  : g_o;

    if (MODE == 1) {
        if (tid < BMT) ts[tid] = g_tok[row0 + tid];
        __syncthreads();
    }

    const float* Bp = Bw + (size_t)e * KDIM * NDIM + blockIdx.x * 128;

    const int arow = tid >> 1, apart = (tid & 1) * 4;
    const int brow = tid >> 5, bcol  = (tid & 31) * 4;
    const size_t aoff = (MODE == 1) ? (size_t)ts[arow] * KDIM
                                    : (size_t)(row0 + arow) * KDIM;
    const float* Ap = A + aoff + apart;

    // prologue: tile 0
    float4 av = *(const float4*)(Ap);
    float4 bv = *(const float4*)(Bp + (size_t)brow * NDIM + bcol);
    As[0][apart + 0][arow] = av.x; As[0][apart + 1][arow] = av.y;
    As[0][apart + 2][arow] = av.z; As[0][apart + 3][arow] = av.w;
    *(float4*)&Bs[0][brow][bcol] = bv;
    __syncthreads();

    float c[8][8] = {};
    const int tx = tid & 15, ty = tid >> 4;
    constexpr int T = KDIM / 8;

    for (int t = 0; t < T; ++t) {
        if (t + 1 < T) {
            const int k0 = (t + 1) * 8;
            av = *(const float4*)(Ap + k0);
            bv = *(const float4*)(Bp + (size_t)(k0 + brow) * NDIM + bcol);
        }
        const int buf = t & 1;
#pragma unroll
        for (int kk = 0; kk < 8; ++kk) {
            float ar[8], br[8];
            *(float4*)&ar[0] = *(const float4*)&As[buf][kk][ty * 8];
            *(float4*)&ar[4] = *(const float4*)&As[buf][kk][ty * 8 + 4];
            *(float4*)&br[0] = *(const float4*)&Bs[buf][kk][tx * 8];
            *(float4*)&br[4] = *(const float4*)&Bs[buf][kk][tx * 8 + 4];
#pragma unroll
            for (int i = 0; i < 8; ++i)
#pragma unroll
                for (int j = 0; j < 8; ++j)
                    c[i][j] += ar[i] * br[j];
        }
        if (t + 1 < T) {
            const int nb = (t + 1) & 1;
            As[nb][apart + 0][arow] = av.x; As[nb][apart + 1][arow] = av.y;
            As[nb][apart + 2][arow] = av.z; As[nb][apart + 3][arow] = av.w;
            *(float4*)&Bs[nb][brow][bcol] = bv;
            __syncthreads();
        }
    }

    // epilogue
    const int ncol0 = blockIdx.x * 128 + tx * 8;
    float bia[8];
#pragma unroll
    for (int j = 0; j < 8; ++j) bia[j] = bias[(size_t)e * NDIM + ncol0 + j];
#pragma unroll
    for (int i = 0; i < 8; ++i) {
        const int r = row0 + ty * 8 + i;
        float* op = Cout + (size_t)r * NDIM + ncol0;
        float v[8];
#pragma unroll
        for (int j = 0; j < 8; ++j) {
            float u = c[i][j] + bia[j];
            if (MODE == 1)   // exact GELU: 0.5*x*(1+erf(x/sqrt(2)))
                u = 0.5f * u * (1.f + erff(u * 0.70710678118654752f));
            v[j] = u;
        }
        *(float4*)&op[0] = *(const float4*)&v[0];
        *(float4*)&op[4] = *(const float4*)&v[4];
    }
}

// out[n,d] = p0 * eo(slot0)[d] + p1 * eo(slot1)[d]
__global__ void combine_k(float* __restrict__ out) {
    int i = blockIdx.x * blockDim.x + threadIdx.x;   // over NTOK * DD/4
    int n  = i >> 8;            // DD/4 = 256 float4 per token
    int d4 = i & 255;
    int   s0 = g_slot[n * 2 + 0], s1 = g_slot[n * 2 + 1];
    float p0 = g_p[n * 2 + 0],    p1 = g_p[n * 2 + 1];
    const float4 a = *(const float4*)&g_o[(size_t)s0 * DD + d4 * 4];
    const float4 b = *(const float4*)&g_o[(size_t)s1 * DD + d4 * 4];
    float4 r;
    r.x = p0 * a.x + p1 * b.x;
    r.y = p0 * a.y + p1 * b.y;
    r.z = p0 * a.z + p1 * b.z;
    r.w = p0 * a.w + p1 * b.w;
    ((float4*)out)[i] = r;
}

// ---------------------------------------------------------------------------
extern "C" void kernel_launch(void* const* d_in, const int* in_sizes, int n_in,
                              void* d_out, int out_size) {
    const float* x  = (const float*)d_in[0];
    const float* Wg = (const float*)d_in[1];
    const float* bg = (const float*)d_in[2];
    const float* W1 = (const float*)d_in[3];
    const float* b1 = (const float*)d_in[4];
    const float* W2 = (const float*)d_in[5];
    const float* b2 = (const float*)d_in[6];
    float* out = (float*)d_out;

    init_k<<<MAXROWS / 256, 256>>>();                       // 68 blocks == MAXROWS
    router_k<<<NTOK / 8, 256>>>(x, Wg, bg);                 // 8 warps/block
    scan_k<<<1, 32>>>();
    scatter_k<<<NTOK / 256, 256>>>();
    gemm_k<DD, HH, 1><<<dim3(HH / 128, MAXROWS / BMT), 256>>>(x, W1, b1);
    gemm_k<HH, DD, 2><<<dim3(DD / 128, MAXROWS / BMT), 256>>>(nullptr, W2, b2);
    combine_k<<<(NTOK * DD / 4) / 256, 256>>>(out);
}

// round 5
// speedup vs baseline: 3.0511x; 3.0511x over previous
#include <cuda_runtime.h>
#include <cuda_fp16.h>
#include <math.h>
#include <stdint.h>

// ---------------------------------------------------------------------------
// MoE: router -> scatter -> fp16x3 mma.sync grouped GEMM1(gelu) -> GEMM2 -> combine
// (tcgen05 unavailable: harness compiles PTX for base sm_103 target)
// ---------------------------------------------------------------------------
#define DD    1024
#define HH    4096
#define EE    8
#define NTOK  8192
#define BMT   128
#define MAXROWS (NTOK*2 + EE*BMT)   // 17408
#define BKH   64                    // K halves per chunk (128B rows, SW128)

// stage: Ah 16K | Al 16K | Bh 16K | Bl 16K  = 64KB, 3 stages
#define OFF_AH  0
#define OFF_AL  16384
#define OFF_BH  32768
#define OFF_BL  49152
#define STAGE   65536
#define NSTG    3
#define GEMM_SMEM (NSTG*STAGE)

// -------- scratch (device globals) -----------------------------------------
__device__ int   g_counts[EE];
__device__ int   g_cursor[EE];
__device__ int   g_off[EE + 1];
__device__ int   g_total;
__device__ int   g_tok[MAXROWS];
__device__ int   g_idx[NTOK * 2];
__device__ int   g_slot[NTOK * 2];
__device__ float g_p[NTOK * 2];

__device__ __align__(256) __half g_w1h[(size_t)EE * HH * DD];  // W1^T [E][H][D]
__device__ __align__(256) __half g_w1l[(size_t)EE * HH * DD];
__device__ __align__(256) __half g_w2h[(size_t)EE * DD * HH];  // W2^T [E][D][H]
__device__ __align__(256) __half g_w2l[(size_t)EE * DD * HH];
__device__ __align__(256) __half g_ah[(size_t)MAXROWS * DD];   // gathered x
__device__ __align__(256) __half g_al[(size_t)MAXROWS * DD];
__device__ __align__(256) __half g_hh[(size_t)MAXROWS * HH];   // gelu(h)
__device__ __align__(256) __half g_hl[(size_t)MAXROWS * HH];
__device__ __align__(256) float  g_o[(size_t)MAXROWS * DD];

// -------- PTX helpers (base sm_103-legal only) ------------------------------
__device__ __forceinline__ uint32_t smem_u32(const void* p) {
    uint32_t a;
    asm("{ .reg .u64 t; cvta.to.shared.u64 t, %1; cvt.u32.u64 %0, t; }"
        : "=r"(a) : "l"(p));
    return a;
}

#define CP_A16(dst, src) \
    asm volatile("cp.async.cg.shared.global [%0], [%1], 16;" \
                 :: "r"(dst), "l"(src))
#define CP_COMMIT() asm volatile("cp.async.commit_group;" ::: "memory")
#define CP_WAIT1()  asm volatile("cp.async.wait_group 1;" ::: "memory")
#define CP_WAIT0()  asm volatile("cp.async.wait_group 0;" ::: "memory")

#define LDSM4(r0, r1, r2, r3, addr) \
    asm volatile("ldmatrix.sync.aligned.m8n8.x4.shared.b16 {%0,%1,%2,%3}, [%4];" \
                 : "=r"(r0), "=r"(r1), "=r"(r2), "=r"(r3) : "r"(addr))

#define HMMA(c, a, b) \
    asm volatile("mma.sync.aligned.m16n8k16.row.col.f32.f16.f16.f32 " \
                 "{%0,%1,%2,%3}, {%4,%5,%6,%7}, {%8,%9}, {%0,%1,%2,%3};" \
                 : "+f"((c)[0]), "+f"((c)[1]), "+f"((c)[2]), "+f"((c)[3]) \
                 : "r"((a)[0]), "r"((a)[1]), "r"((a)[2]), "r"((a)[3]), \
                   "r"((b)[0]), "r"((b)[1]))

// -------- small kernels ----------------------------------------------------
__global__ void init_k() {
    int i = blockIdx.x * blockDim.x + threadIdx.x;
    if (i < EE) g_counts[i] = 0;
    if (i < MAXROWS) g_tok[i] = 0;
}

__global__ void router_k(const float* __restrict__ x,
                         const float* __restrict__ Wg,
                         const float* __restrict__ bg) {
    int warp = (blockIdx.x * blockDim.x + threadIdx.x) >> 5;
    int lane = threadIdx.x & 31;
    if (warp >= NTOK) return;
    const float* xr = x + (size_t)warp * DD;
    float acc[EE];
#pragma unroll
    for (int e = 0; e < EE; e++) acc[e] = 0.f;
#pragma unroll
    for (int i = 0; i < DD / 32; i++) {
        float xv = xr[lane + 32 * i];
        const float* wr = Wg + (size_t)(lane + 32 * i) * EE;
#pragma unroll
        for (int e = 0; e < EE; e++) acc[e] += xv * wr[e];
    }
#pragma unroll
    for (int e = 0; e < EE; e++)
#pragma unroll
        for (int o = 16; o > 0; o >>= 1)
            acc[e] += __shfl_xor_sync(0xffffffffu, acc[e], o);
    if (lane == 0) {
        float l[EE];
        float m = -1e30f;
#pragma unroll
        for (int e = 0; e < EE; e++) { l[e] = acc[e] + bg[e]; m = fmaxf(m, l[e]); }
        float s = 0.f;
#pragma unroll
        for (int e = 0; e < EE; e++) s += expf(l[e] - m);
        int i0 = 0;
#pragma unroll
        for (int e = 1; e < EE; e++) if (l[e] > l[i0]) i0 = e;
        int i1 = (i0 == 0) ? 1 : 0;
#pragma unroll
        for (int e = 0; e < EE; e++) if (e != i0 && l[e] > l[i1]) i1 = e;
        g_idx[warp * 2 + 0] = i0;  g_p[warp * 2 + 0] = expf(l[i0] - m) / s;
        g_idx[warp * 2 + 1] = i1;  g_p[warp * 2 + 1] = expf(l[i1] - m) / s;
        atomicAdd(&g_counts[i0], 1);
        atomicAdd(&g_counts[i1], 1);
    }
}

__global__ void scan_k() {
    if (threadIdx.x == 0) {
        int off = 0;
        for (int e = 0; e < EE; e++) {
            g_off[e] = off;
            g_cursor[e] = off;
            off += (g_counts[e] + BMT - 1) / BMT * BMT;
        }
        g_off[EE] = off;
        g_total = off;
    }
}

__global__ void scatter_k() {
    int n = blockIdx.x * blockDim.x + threadIdx.x;
    if (n >= NTOK) return;
#pragma unroll
    for (int k = 0; k < 2; k++) {
        int e = g_idx[n * 2 + k];
        int pos = atomicAdd(&g_cursor[e], 1);
        g_tok[pos] = n;
        g_slot[n * 2 + k] = pos;
    }
}

// gather x rows per slot + split fp32 -> fp16 hi/lo
__global__ void pregather_k(const float* __restrict__ x) {
    int row = blockIdx.x, tid = threadIdx.x;
    int tok = g_tok[row];
    float4 v = ((const float4*)(x + (size_t)tok * DD))[tid];
    __half h0 = __float2half(v.x), h1 = __float2half(v.y);
    __half h2 = __float2half(v.z), h3 = __float2half(v.w);
    __half2 hA; hA.x = h0; hA.y = h1;
    __half2 hB; hB.x = h2; hB.y = h3;
    __half2 lA, lB;
    lA.x = __float2half(v.x - __half2float(h0));
    lA.y = __float2half(v.y - __half2float(h1));
    lB.x = __float2half(v.z - __half2float(h2));
    lB.y = __float2half(v.w - __half2float(h3));
    ((uint2*)(g_ah + (size_t)row * DD))[tid] =
        make_uint2(*(uint32_t*)&hA, *(uint32_t*)&hB);
    ((uint2*)(g_al + (size_t)row * DD))[tid] =
        make_uint2(*(uint32_t*)&lA, *(uint32_t*)&lB);
}

// transpose in[e][R][C] fp32 -> out_hi/lo[e][C][R] fp16
__global__ void transconv_k(const float* __restrict__ in,
                            __half* __restrict__ oh,
                            __half* __restrict__ ol,
                            int R, int C) {
    __shared__ float t[32][33];
    int e = blockIdx.z;
    const float* ip = in + (size_t)e * R * C;
    size_t ob = (size_t)e * R * C;
    int c0 = blockIdx.x * 32, r0 = blockIdx.y * 32;
#pragma unroll
    for (int i = threadIdx.y; i < 32; i += 8)
        t[i][threadIdx.x] = ip[(size_t)(r0 + i) * C + c0 + threadIdx.x];
    __syncthreads();
#pragma unroll
    for (int i = threadIdx.y; i < 32; i += 8) {
        float v = t[threadIdx.x][i];
        __half h = __float2half(v);
        size_t o = ob + (size_t)(c0 + i) * R + r0 + threadIdx.x;
        oh[o] = h;
        ol[o] = __float2half(v - __half2float(h));
    }
}

// ---------------------------------------------------------------------------
// fp16x3 mma.sync grouped GEMM.  C[128 x 128] per block.
// MODE 1: A=g_ah/al, out->g_hh/g_hl (bias+gelu, fp16 split)
// MODE 2: A=g_hh/hl, out->g_o (bias, fp32)
// SMEM rows: 64 halves = 128B, SW128 chunk swizzle, conflict-free ldmatrix.
// ---------------------------------------------------------------------------
template <int KDIM>
__device__ __forceinline__ void load_stage(
    uint32_t stu,
    const __half* __restrict__ Ahp, const __half* __restrict__ Alp,
    const __half* __restrict__ Bhp, const __half* __restrict__ Blp,
    int kof, int tid) {
#pragma unroll
    for (int it = 0; it < 4; ++it) {
        int idx = it * 256 + tid;
        int r = idx >> 3, c = idx & 7;
        uint32_t d = (uint32_t)(r * 128 + ((c ^ (r & 7)) << 4));
        size_t src = (size_t)r * KDIM + kof + c * 8;
        CP_A16(stu + OFF_AH + d, Ahp + src);
        CP_A16(stu + OFF_AL + d, Alp + src);
        CP_A16(stu + OFF_BH + d, Bhp + src);
        CP_A16(stu + OFF_BL + d, Blp + src);
    }
}

template <int KDIM, int NDIM, int MODE>
__global__ __launch_bounds__(256, 1)
void gemm_hmma(const __half* __restrict__ Ah, const __half* __restrict__ Al,
               const __half* __restrict__ Bh, const __half* __restrict__ Bl,
               const float* __restrict__ bias) {
    const int row0 = blockIdx.y * BMT;
    if (row0 >= g_total) return;
    int e = 0;
    while (row0 >= g_off[e + 1]) ++e;
    const int nbase = blockIdx.x * 128;

    extern __shared__ __align__(128) char dsmem[];
    const uint32_t smem_u = smem_u32(dsmem);

    const int tid = threadIdx.x;
    const int lane = tid & 31;
    const int wid = tid >> 5;
    const int warp_m = wid & 3;   // 4 warps in M (32 rows each)
    const int warp_n = wid >> 2;  // 2 warps in N (64 cols each)

    const __half* Ahp = Ah + (size_t)row0 * KDIM;
    const __half* Alp = Al + (size_t)row0 * KDIM;
    const __half* Bhp = Bh + ((size_t)e * NDIM + nbase) * KDIM;
    const __half* Blp = Bl + ((size_t)e * NDIM + nbase) * KDIM;

    constexpr int NC = KDIM / BKH;

    // prologue: first NSTG-1 chunks
#pragma unroll
    for (int p = 0; p < NSTG - 1; ++p) {
        load_stage<KDIM>(smem_u + p * STAGE, Ahp, Alp, Bhp, Blp, p * BKH, tid);
        CP_COMMIT();
    }

    float acc[2][8][4] = {};

    for (int kc = 0; kc < NC; ++kc) {
        if (kc + 1 < NC) CP_WAIT1(); else CP_WAIT0();
        __syncthreads();

        const uint32_t stu = smem_u + (kc % NSTG) * STAGE;
#pragma unroll
        for (int ks = 0; ks < 4; ++ks) {         // 4 x k16 within BK=64
            uint32_t aH[2][4], aL[2][4], bH[8][2], bL[8][2];
#pragma unroll
            for (int mi = 0; mi < 2; ++mi) {
                int tile = lane >> 3;
                int row = warp_m * 32 + mi * 16 + (lane & 7) + ((tile & 1) << 3);
                int kc8 = ks * 2 + (tile >> 1);
                uint32_t off = (uint32_t)(row * 128 + ((kc8 ^ (row & 7)) << 4));
                LDSM4(aH[mi][0], aH[mi][1], aH[mi][2], aH[mi][3], stu + OFF_AH + off);
                LDSM4(aL[mi][0], aL[mi][1], aL[mi][2], aL[mi][3], stu + OFF_AL + off);
            }
#pragma unroll
            for (int ng = 0; ng < 4; ++ng) {
                int row = warp_n * 64 + ng * 16 + ((lane >> 4) << 3) + (lane & 7);
                int kc8 = ks * 2 + ((lane >> 3) & 1);
                uint32_t off = (uint32_t)(row * 128 + ((kc8 ^ (row & 7)) << 4));
                LDSM4(bH[2 * ng][0], bH[2 * ng][1], bH[2 * ng + 1][0], bH[2 * ng + 1][1],
                      stu + OFF_BH + off);
                LDSM4(bL[2 * ng][0], bL[2 * ng][1], bL[2 * ng + 1][0], bL[2 * ng + 1][1],
                      stu + OFF_BL + off);
            }
            // pass-major ordering: long gaps between reuses of each accumulator
#pragma unroll
            for (int mi = 0; mi < 2; ++mi)
#pragma unroll
                for (int nt = 0; nt < 8; ++nt) HMMA(acc[mi][nt], aH[mi], bH[nt]);
#pragma unroll
            for (int mi = 0; mi < 2; ++mi)
#pragma unroll
                for (int nt = 0; nt < 8; ++nt) HMMA(acc[mi][nt], aH[mi], bL[nt]);
#pragma unroll
            for (int mi = 0; mi < 2; ++mi)
#pragma unroll
                for (int nt = 0; nt < 8; ++nt) HMMA(acc[mi][nt], aL[mi], bH[nt]);
        }
        __syncthreads();
        if (kc + NSTG - 1 < NC) {
            load_stage<KDIM>(smem_u + ((kc + NSTG - 1) % NSTG) * STAGE,
                             Ahp, Alp, Bhp, Blp, (kc + NSTG - 1) * BKH, tid);
            CP_COMMIT();
        }
    }

    // epilogue
    const int gr = lane >> 2;
    const int gc = (lane & 3) * 2;
#pragma unroll
    for (int mi = 0; mi < 2; ++mi) {
        const int rb = row0 + warp_m * 32 + mi * 16 + gr;
#pragma unroll
        for (int nt = 0; nt < 8; ++nt) {
            const int col = nbase + warp_n * 64 + nt * 8 + gc;
            const float2 bv = *(const float2*)(bias + (size_t)e * NDIM + col);
#pragma unroll
            for (int h = 0; h < 2; ++h) {   // rows gr and gr+8
                const int r = rb + h * 8;
                float u0 = acc[mi][nt][2 * h]     + bv.x;
                float u1 = acc[mi][nt][2 * h + 1] + bv.y;
                if (MODE == 1) {
                    u0 = 0.5f * u0 * (1.f + erff(u0 * 0.70710678118654752f));
                    u1 = 0.5f * u1 * (1.f + erff(u1 * 0.70710678118654752f));
                    __half h0 = __float2half(u0), h1 = __float2half(u1);
                    __half2 hv; hv.x = h0; hv.y = h1;
                    __half2 lv;
                    lv.x = __float2half(u0 - __half2float(h0));
                    lv.y = __float2half(u1 - __half2float(h1));
                    *(__half2*)(g_hh + (size_t)r * HH + col) = hv;
                    *(__half2*)(g_hl + (size_t)r * HH + col) = lv;
                } else {
                    float2 ov; ov.x = u0; ov.y = u1;
                    *(float2*)(g_o + (size_t)r * NDIM + col) = ov;
                }
            }
        }
    }
}

// out[n,d] = p0 * g_o[slot0][d] + p1 * g_o[slot1][d]
__global__ void combine_k(float* __restrict__ out) {
    int i = blockIdx.x * blockDim.x + threadIdx.x;
    int n = i >> 8, d4 = i & 255;
    int   s0 = g_slot[n * 2 + 0], s1 = g_slot[n * 2 + 1];
    float p0 = g_p[n * 2 + 0],    p1 = g_p[n * 2 + 1];
    const float4 a = *(const float4*)&g_o[(size_t)s0 * DD + d4 * 4];
    const float4 b = *(const float4*)&g_o[(size_t)s1 * DD + d4 * 4];
    float4 r;
    r.x = p0 * a.x + p1 * b.x;
    r.y = p0 * a.y + p1 * b.y;
    r.z = p0 * a.z + p1 * b.z;
    r.w = p0 * a.w + p1 * b.w;
    ((float4*)out)[i] = r;
}

// ---------------------------------------------------------------------------
extern "C" void kernel_launch(void* const* d_in, const int* in_sizes, int n_in,
                              void* d_out, int out_size) {
    const float* x  = (const float*)d_in[0];
    const float* Wg = (const float*)d_in[1];
    const float* bg = (const float*)d_in[2];
    const float* W1 = (const float*)d_in[3];
    const float* b1 = (const float*)d_in[4];
    const float* W2 = (const float*)d_in[5];
    const float* b2 = (const float*)d_in[6];
    float* out = (float*)d_out;

    cudaFuncSetAttribute(gemm_hmma<DD, HH, 1>,
                         cudaFuncAttributeMaxDynamicSharedMemorySize, GEMM_SMEM);
    cudaFuncSetAttribute(gemm_hmma<HH, DD, 2>,
                         cudaFuncAttributeMaxDynamicSharedMemorySize, GEMM_SMEM);

    __half *w1h, *w1l, *w2h, *w2l, *ah, *al, *hh, *hl;
    cudaGetSymbolAddress((void**)&w1h, g_w1h);
    cudaGetSymbolAddress((void**)&w1l, g_w1l);
    cudaGetSymbolAddress((void**)&w2h, g_w2h);
    cudaGetSymbolAddress((void**)&w2l, g_w2l);
    cudaGetSymbolAddress((void**)&ah,  g_ah);
    cudaGetSymbolAddress((void**)&al,  g_al);
    cudaGetSymbolAddress((void**)&hh,  g_hh);
    cudaGetSymbolAddress((void**)&hl,  g_hl);

    init_k<<<MAXROWS / 256, 256>>>();
    router_k<<<NTOK / 8, 256>>>(x, Wg, bg);
    scan_k<<<1, 32>>>();
    scatter_k<<<NTOK / 256, 256>>>();
    pregather_k<<<MAXROWS, 256>>>(x);
    // W1[e][D][H] -> [e][H][D] ; W2[e][H][D] -> [e][D][H]
    transconv_k<<<dim3(HH / 32, DD / 32, EE), dim3(32, 8)>>>(W1, w1h, w1l, DD, HH);
    transconv_k<<<dim3(DD / 32, HH / 32, EE), dim3(32, 8)>>>(W2, w2h, w2l, HH, DD);

    gemm_hmma<DD, HH, 1><<<dim3(HH / 128, MAXROWS / BMT), 256, GEMM_SMEM>>>(
        ah, al, w1h, w1l, b1);
    gemm_hmma<HH, DD, 2><<<dim3(DD / 128, MAXROWS / BMT), 256, GEMM_SMEM>>>(
        hh, hl, w2h, w2l, b2);

    combine_k<<<(NTOK * DD / 4) / 256, 256>>>(out);
}